// round 17
// baseline (speedup 1.0000x reference)
#include <cuda_runtime.h>

// ---------------- problem constants ----------------
#define NZ     300
#define NX     400
#define NPML   32
#define NZP    (NZ + 2*NPML)            // 364
#define NXP    (NX + 2*NPML)            // 464
#define NXPP   480                      // global row pitch (floats)
#define NSTEPS 200
#define NSHOTS 2
#define DXC    0.01f
#define DTC    0.001f
#define SRC_Z  (NPML + 2)               // 34
#define REC_Z  (NPML + 2)               // 34

#define FSZ (NZP * NXPP)

#define BLKS_PER_SHOT 74
#define NBLK   (NSHOTS * BLKS_PER_SHOT) // 148
#define NTHR   1024
#define MAXC   3                        // padded cells: nrows*480 <= 2400 -> 3 chunks

// smem tile: row r <-> global row z0-2+r
//   r=0 guard(0), r=1 = z0-1 (vx/vz imported, sxz recomputed),
//   r=2..nrows+1 owned, r=nrows+2 = z1 (vx/vz imported, szz recomputed)
#define SROWS  8
#define SPITCH 480                      // divisible by 32 -> warp-aligned rows
#define FTILE  (SROWS * SPITCH)
#define SMEM_DYN (5 * FTILE * 4)        // 76800 B

// enc = soff | flags<<20
#define F_VAL  1
#define F_REC  2
#define F_SRC  4
#define F_TOP  8     // r == 2        -> publish vx,vz to lo
#define F_BOT  16    // r == nrows+1  -> publish vx,vz to hi
#define F_WACT 32    // warp has at least one valid cell (warp-uniform)

// ---------------- device state (static, no allocs) ----------------
// Parity double-buffered velocity exchange (overrun-proof; see R15 proof:
// rewrite of parity p at t+2 requires neighbor flag q_{t+1}, which requires
// the neighbor's import of parity p at step t to have completed).
__device__ float g_vx[2][NSHOTS][FSZ];
__device__ float g_vz[2][NSHOTS][FSZ];

__device__ unsigned g_flags[NBLK * 32];   // monotonic, 128B apart
__device__ double   g_part[NBLK];
__device__ unsigned g_done = 0u;

__device__ __forceinline__ void st_release_u32(unsigned* p, unsigned v)
{
    asm volatile("st.release.gpu.global.u32 [%0], %1;" :: "l"(p), "r"(v) : "memory");
}
__device__ __forceinline__ unsigned ld_acquire_u32(const unsigned* p)
{
    unsigned v;
    asm volatile("ld.acquire.gpu.global.u32 %0, [%1];" : "=r"(v) : "l"(p) : "memory");
    return v;
}
__device__ __forceinline__ void wait_flag(const unsigned* f, unsigned q)
{
    while ((int)(ld_acquire_u32(f) - q) < 0) { }
}

__global__ void __launch_bounds__(NTHR, 1)
fwi_persistent(const float* __restrict__ Vp,
               const float* __restrict__ Vs,
               const float* __restrict__ Den,
               const float* __restrict__ Stf,
               const float* __restrict__ Mask,
               const int*   __restrict__ ShotIds,
               float*       __restrict__ out)
{
    extern __shared__ float sm[];
    float* __restrict__ s_vx  = sm;
    float* __restrict__ s_vz  = sm + 1 * FTILE;
    float* __restrict__ s_sxx = sm + 2 * FTILE;   // lane0 columns only (read by lane31 fallback)
    float* __restrict__ s_szz = sm + 3 * FTILE;
    float* __restrict__ s_sxz = sm + 4 * FTILE;

    const int b   = blockIdx.x;
    const int s   = b / BLKS_PER_SHOT;
    const int kk  = b - s * BLKS_PER_SHOT;
    const int z0  = (kk * NZP) / BLKS_PER_SHOT;
    const int z1  = ((kk + 1) * NZP) / BLKS_PER_SHOT;
    const int nrows = z1 - z0;
    const int tid  = threadIdx.x;
    const int lane = tid & 31;

    const int nb_lo = (kk > 0)                 ? b - 1 : -1;
    const int nb_hi = (kk < BLKS_PER_SHOT - 1) ? b + 1 : -1;

    const int gbase = (z0 - 2) * NXPP;     // global offset of smem row 0

    unsigned  q      = *(volatile unsigned*)&g_flags[b * 32];   // replay-safe base
    unsigned* myflag = &g_flags[b * 32];

    // ---------- zero smem tiles ----------
    for (int c = tid; c < 5 * FTILE; c += NTHR) sm[c] = 0.0f;

    // ---------- coefficient helper (A = dt*(lam+2mu)/dx, C = dt*mu/dx) ----------
    auto coef = [&](int i, int j, float& dtr, float& dmp, float& a, float& cc) {
        int jm = min(j, NXP - 1);
        int ip = min(max(i - NPML, 0), NZ - 1);
        int jp = min(max(jm - NPML, 0), NX - 1);
        float vp  = Vp [ip * NX + jp];
        float vs  = Vs [ip * NX + jp];
        float den = Den[ip * NX + jp];
        float m   = Mask[i * NXP + jm];
        vp  = m * vp  + (1.0f - m) * vp;
        vs  = m * vs  + (1.0f - m) * vs;
        den = m * den + (1.0f - m) * den;
        float mu  = vs * vs * den * 1e-6f;
        float lam = (vp * vp - 2.0f * vs * vs) * den * 1e-6f;
        const float inv_dx = 1.0f / DXC;
        a   = DTC * (lam + 2.0f * mu) * inv_dx;
        cc  = DTC * mu  * inv_dx;
        dtr = (DTC / den) * inv_dx;
        float a1 = (float)(NPML - i);
        float a2 = (float)(i - (NZP - 1 - NPML));
        float dz = fmaxf(a1, a2); dz = fminf(fmaxf(dz, 0.0f), (float)NPML) / (float)NPML;
        float b1 = (float)(NPML - jm);
        float b2 = (float)(jm - (NXP - 1 - NPML));
        float dxs = fmaxf(b1, b2); dxs = fminf(fmaxf(dxs, 0.0f), (float)NPML) / (float)NPML;
        dmp = expf(-0.1f * (dz * dz + dxs * dxs));
    };

    const int sid  = ShotIds[s];
    const int srcx = NPML + 20 + sid * ((NX - 40) / NSHOTS);
    const float* stf = Stf + sid * NSTEPS;

    // ---------- per-thread padded cells (boundary rows FIRST, warp-aligned rows) ----------
    // padded cell c: rowk = c/480, j = c%480; rowk 0 -> r=2 (z0), rowk 1 -> r=nrows+1
    // (z1-1), rowk>=2 -> r=rowk+1 (interior). Valid iff rowk<nrows && j<464.
    unsigned enc[MAXC];
    float cdm[MAXC], cdt[MAXC], cA[MAXC], cC[MAXC];
    float rvx[MAXC], rvz[MAXC], rsxx[MAXC], rszz[MAXC], rsxz[MAXC];

    #pragma unroll
    for (int k = 0; k < MAXC; ++k) {
        int c    = tid + k * NTHR;
        int rowk = c / SPITCH;
        int j    = c - rowk * SPITCH;
        int wact = (((c & ~31)) < nrows * SPITCH);   // warp-uniform activity
        int rvalid = (rowk < nrows);
        int rk  = rvalid ? rowk : 0;
        int r   = (rk == 0) ? 2 : ((rk == 1) ? (nrows + 1) : (rk + 1));
        int i   = z0 - 2 + r;
        int v   = rvalid && (j < NXP);

        int f = v ? F_VAL : 0;
        if (wact) f |= F_WACT;
        if (v && i == REC_Z && j >= NPML && j < NPML + NX) f |= F_REC;
        if (v && i == SRC_Z && j == srcx)                  f |= F_SRC;
        if (v && r == 2)          f |= F_TOP;
        if (v && r == nrows + 1)  f |= F_BOT;
        enc[k] = (unsigned)(r * SPITCH + j) | ((unsigned)f << 20);

        float dtr, dmp, a, cc;
        coef(i, j, dtr, dmp, a, cc);
        cdt[k] = dtr; cdm[k] = dmp; cA[k] = a; cC[k] = cc;
        rvx[k] = 0.0f; rvz[k] = 0.0f; rsxx[k] = 0.0f; rszz[k] = 0.0f; rsxz[k] = 0.0f;
    }

    // ---------- stress-halo recompute cells ----------
    const bool topH = (nb_lo >= 0 && tid < NXP);
    const bool botH = (nb_hi >= 0 && tid >= 512 && tid < 512 + NXP);
    float hCt = 0.0f, hdampT = 0.0f;           // top: mu coeff + damp (sxz)
    float hA = 0.0f, hCb = 0.0f, hdampB = 0.0f;// bottom: A, C + damp (szz)
    bool  srcB = false;
    if (topH) {
        float dtr, a;
        coef(z0 - 1, tid, dtr, hdampT, a, hCt);
    }
    if (botH) {
        int j = tid - 512;
        float dtr;
        coef(z1, j, dtr, hdampB, hA, hCb);
        srcB = (z1 == SRC_Z && j == srcx);
    }

    __syncthreads();   // smem zero + setup done (block-local)

    double acc = 0.0;

    const int topSO = 1 * SPITCH;              // row z0-1
    const int botSO = (nrows + 2) * SPITCH;    // row z1

    // ---------------- time loop ----------------
    for (int t = 0; t < NSTEPS; ++t) {
        const int p = t & 1;
        float* __restrict__ vxg = g_vx[p][s];
        float* __restrict__ vzg = g_vz[p][s];

        // ---- velocity body: centers in regs, horizontal neighbors via shfl ----
        auto vcell = [&](int k) {
            const int f = (int)(enc[k] >> 20);
            if (!(f & F_WACT)) return;                       // warp-uniform skip
            const int so = (int)(enc[k] & 0xFFFFFu);
            float sxx_r = __shfl_down_sync(0xFFFFFFFFu, rsxx[k], 1);
            float sxz_l = __shfl_up_sync  (0xFFFFFFFFu, rsxz[k], 1);
            if (lane == 31) sxx_r = s_sxx[so + 1];           // lane0 column of next warp
            if (lane == 0)  sxz_l = s_sxz[so - 1];
            float sxz_u = s_sxz[so - SPITCH];
            float szz_d = s_szz[so + SPITCH];
            float nvx = (rvx[k] + cdt[k] * ((sxx_r - rsxx[k]) + (rsxz[k] - sxz_u))) * cdm[k];
            float nvz = (rvz[k] + cdt[k] * ((rsxz[k] - sxz_l) + (szz_d - rszz[k]))) * cdm[k];
            if (f & F_VAL) {
                rvx[k] = nvx;
                rvz[k] = nvz;
                s_vx[so] = nvx;
                s_vz[so] = nvz;
                if (f & (F_TOP | F_BOT)) {
                    __stcg(&vxg[gbase + so], nvx);
                    __stcg(&vzg[gbase + so], nvz);
                }
                if (f & F_REC) acc += (double)nvx * (double)nvx;
            }
        };

        // ===== velocity phase =====
        vcell(0);                                  // rows z0 and z1-1 live entirely in chunk 0
        __syncthreads();                           // bar1
        ++q;
        if (tid == 0) st_release_u32(myflag, q);   // publish V(t) boundary

        vcell(1);                                  // mattress part 1 (flag propagates)

        float hvx = 0.0f, hvz = 0.0f;
        if (topH) {
            wait_flag(&g_flags[nb_lo * 32], q);
            hvx = __ldcg(&vxg[(z0 - 1) * NXPP + tid]);
            hvz = __ldcg(&vzg[(z0 - 1) * NXPP + tid]);
        }
        if (botH) {
            int j = tid - 512;
            wait_flag(&g_flags[nb_hi * 32], q);
            hvx = __ldcg(&vxg[z1 * NXPP + j]);
            hvz = __ldcg(&vzg[z1 * NXPP + j]);
        }

        vcell(2);                                  // mattress part 2 (hides ldcg)

        if (topH) { s_vx[topSO + tid] = hvx; s_vz[topSO + tid] = hvz; }
        if (botH) { int j = tid - 512; s_vx[botSO + j] = hvx; s_vz[botSO + j] = hvz; }
        __syncthreads();                           // bar2: all velocity ready

        // ---- stress body: centers in regs, horizontal neighbors via shfl ----
        auto scell = [&](int k) {
            const int f = (int)(enc[k] >> 20);
            if (!(f & F_WACT)) return;
            const int so = (int)(enc[k] & 0xFFFFFu);
            float vx_l = __shfl_up_sync  (0xFFFFFFFFu, rvx[k], 1);
            float vz_r = __shfl_down_sync(0xFFFFFFFFu, rvz[k], 1);
            if (lane == 0)  vx_l = s_vx[so - 1];
            if (lane == 31) vz_r = s_vz[so + 1];
            float vx_d = s_vx[so + SPITCH];
            float vz_u = s_vz[so - SPITCH];
            float dx = rvx[k] - vx_l;
            float dz = rvz[k] - vz_u;
            float B = cA[k] - 2.0f * cC[k];
            float sxxn = (rsxx[k] + cA[k] * dx + B * dz) * cdm[k];
            float szzn = (rszz[k] + B * dx + cA[k] * dz) * cdm[k];
            float sxzn = (rsxz[k] + cC[k] * ((vx_d - rvx[k]) + (vz_r - rvz[k]))) * cdm[k];
            if (f & F_SRC) {
                float sv = stf[t] * DTC;
                sxxn += sv;
                szzn += sv;
            }
            if (f & F_VAL) {
                rsxx[k] = sxxn; rszz[k] = szzn; rsxz[k] = sxzn;
                s_szz[so] = szzn;
                s_sxz[so] = sxzn;
                if (lane == 0) s_sxx[so] = sxxn;   // only lane0 columns ever read
            }
        };

        // ===== stress phase + stress-halo recompute =====
        scell(0); scell(1); scell(2);

        if (topH) {   // sxz(z0-1): bit-identical recompute of lo neighbor's row
            const int so = topSO + tid;
            float v = (s_sxz[so] + hCt * ((s_vx[so + SPITCH] - s_vx[so])
                                        + (s_vz[so + 1]      - s_vz[so]))) * hdampT;
            s_sxz[so] = v;
        }
        if (botH) {   // szz(z1): same B = A - 2C derivation as owned cells
            const int j  = tid - 512;
            const int so = botSO + j;
            float dx = s_vx[so] - s_vx[so - 1];
            float dz = s_vz[so] - s_vz[so - SPITCH];
            float Bb = hA - 2.0f * hCb;
            float v = (s_szz[so] + Bb * dx + hA * dz) * hdampB;
            if (srcB) v += stf[t] * DTC;
            s_szz[so] = v;
        }
        __syncthreads();                           // bar3
    }

    // ---------------- deterministic reduction ----------------
    __shared__ double sh[NTHR];
    sh[tid] = acc;
    __syncthreads();
    for (int o = NTHR / 2; o > 0; o >>= 1) {
        if (tid < o) sh[tid] += sh[tid + o];
        __syncthreads();
    }

    __shared__ int is_last;
    if (tid == 0) {
        g_part[b] = sh[0];
        __threadfence();
        unsigned ticket = atomicAdd(&g_done, 1u);
        is_last = ((ticket + 1u) % NBLK == 0u) ? 1 : 0;
    }
    __syncthreads();

    if (is_last) {
        __threadfence();
        double a = 0.0;
        if (tid < NBLK) a = __ldcg(&g_part[tid]);
        sh[tid] = a;
        __syncthreads();
        for (int o = NTHR / 2; o > 0; o >>= 1) {
            if (tid < o) sh[tid] += sh[tid + o];
            __syncthreads();
        }
        if (tid == 0) out[0] = (float)(0.5 * sh[0]);
    }
}

// ---------------- launcher ----------------
extern "C" void kernel_launch(void* const* d_in, const int* in_sizes, int n_in,
                              void* d_out, int out_size)
{
    const float* Vp      = (const float*)d_in[0];
    const float* Vs      = (const float*)d_in[1];
    const float* Den     = (const float*)d_in[2];
    const float* Stf     = (const float*)d_in[3];
    const float* Mask    = (const float*)d_in[4];
    const int*   ShotIds = (const int*)  d_in[5];
    float*       out     = (float*)d_out;
    (void)in_sizes; (void)n_in; (void)out_size;

    static int smem_set = 0;
    if (!smem_set) {
        cudaFuncSetAttribute(fwi_persistent,
                             cudaFuncAttributeMaxDynamicSharedMemorySize, SMEM_DYN);
        smem_set = 1;
    }

    fwi_persistent<<<NBLK, NTHR, SMEM_DYN>>>(Vp, Vs, Den, Stf, Mask, ShotIds, out);
}